// round 9
// baseline (speedup 1.0000x reference)
#include <cuda_runtime.h>

#define NROWS  512
#define DDIM   512
#define TILE   64
#define NT     8            // 512/64 tile-rows
#define NTILES 36           // upper triangle of 8x8
#define KSPLIT 4
#define KLEN   128          // 512/KSPLIT
#define GEMM_GRID (NTILES * KSPLIT)   // 144 blocks ~ one wave
#define POSCAP 32           // max positives per anchor (expected ~4; P(>32) ~ 1e-10)

// Scratch (allocation-free rule: __device__ globals)
__device__ float g_part[KSPLIT * NROWS * NROWS];  // k-split partial dots
__device__ float g_inv[NROWS];                    // 1/max(norm,eps)
__device__ int   g_cls[NROWS];                    // class ids (normalized int)
__device__ float g_posm1[NROWS][POSCAP];          // cos(pos) - 1  (margin baked)
__device__ int   g_np[NROWS];                     // positives count per anchor
__device__ int   g_cnt[NTILES];                   // tile arrival counters (winners reset)

// ---------------------------------------------------------------------------
// Kernel A: prep. 64 blocks x 256 threads, warp-per-anchor (i = w*64 + bid).
// Per warp: row-i norm, ballot-compact positive j's (same class, j > i),
// compute cos(i,j) directly from embs (recomputes norm_j locally - trivial).
// Stores posm1 = cos - 1, np, inv. Block 0: probe dtype, publish g_cls, out=0.
// ---------------------------------------------------------------------------
__global__ void prep_kernel(const float* __restrict__ embs,
                            const void* __restrict__ idxraw,
                            float* __restrict__ out) {
    const int tid  = threadIdx.x;
    const int w    = tid >> 5;
    const int lane = tid & 31;

    __shared__ int s_cls[NROWS];
    __shared__ int fl;
    __shared__ int s_pj[8][POSCAP];

    // Dtype probe (per-block, self-contained): odd int32 positions within the
    // first 2048 bytes. int64 layout -> all zero high words; int32 -> class ids.
    if (tid == 0) fl = 0;
    __syncthreads();
    if (((const int*)idxraw)[2 * tid + 1] != 0) atomicOr(&fl, 1);
    __syncthreads();
    const int is32 = fl;
    const int* __restrict__ i32p = (const int*)idxraw;
    const long long* __restrict__ i64p = (const long long*)idxraw;

#pragma unroll
    for (int e = 0; e < 2; e++) {
        int r = tid + e * 256;
        s_cls[r] = is32 ? i32p[r] : (int)i64p[r];
    }
    __syncthreads();
    if (blockIdx.x == 0) {
        if (tid == 0) *out = 0.0f;
#pragma unroll
        for (int e = 0; e < 2; e++) { int r = tid + e * 256; g_cls[r] = s_cls[r]; }
    }

    const int i = w * 64 + blockIdx.x;     // anchor
    const float* __restrict__ rowp = embs + i * DDIM + lane * 4;
    float4 av[4];
#pragma unroll
    for (int q = 0; q < 4; q++) av[q] = *(const float4*)(rowp + q * 128);

    float dii = 0.f;
#pragma unroll
    for (int q = 0; q < 4; q++)
        dii += av[q].x * av[q].x + av[q].y * av[q].y +
               av[q].z * av[q].z + av[q].w * av[q].w;
#pragma unroll
    for (int o = 16; o; o >>= 1) dii += __shfl_xor_sync(0xffffffffu, dii, o);
    const float invi = 1.0f / fmaxf(sqrtf(dii), 1e-8f);
    if (lane == 0) g_inv[i] = invi;

    // Ballot-compact positive indices (uniform 16 iterations, no divergence).
    const int ci = s_cls[i];
    int np = 0;
#pragma unroll
    for (int slot = 0; slot < 16; slot++) {
        int j = i + 1 + lane + slot * 32;
        bool match = (j < NROWS) && (s_cls[j] == ci);
        unsigned m = __ballot_sync(0xffffffffu, match);
        if (match) {
            int off = np + __popc(m & ((1u << lane) - 1u));
            if (off < POSCAP) s_pj[w][off] = j;
        }
        np += __popc(m);
    }
    if (np > POSCAP) np = POSCAP;
    __syncwarp();
    if (lane == 0) g_np[i] = np;

    // Positive cos values: full warp per positive (dot(i,j) and dot(j,j)).
    for (int p = 0; p < np; p++) {
        int j = s_pj[w][p];
        const float* __restrict__ rj = embs + j * DDIM + lane * 4;
        float dij = 0.f, djj = 0.f;
#pragma unroll
        for (int q = 0; q < 4; q++) {
            float4 b = *(const float4*)(rj + q * 128);
            dij += av[q].x * b.x + av[q].y * b.y + av[q].z * b.z + av[q].w * b.w;
            djj += b.x * b.x + b.y * b.y + b.z * b.z + b.w * b.w;
        }
#pragma unroll
        for (int o = 16; o; o >>= 1) {
            dij += __shfl_xor_sync(0xffffffffu, dij, o);
            djj += __shfl_xor_sync(0xffffffffu, djj, o);
        }
        if (lane == 0) {
            float invj = 1.0f / fmaxf(sqrtf(djj), 1e-8f);
            g_posm1[i][p] = dij * invi * invj - 1.0f;   // margin baked in
        }
    }
}

// ---------------------------------------------------------------------------
// Kernel B: GEMM + fused triplet reduction. 144 blocks x 256 threads.
// Mainloop identical to R8 (64x64 upper tiles x 4 k-split, 4x4 micro-tile,
// XOR-swizzled staging). Then: store partials -> fence -> sync -> per-tile
// arrival counter; last arriver re-reads all 4 partials in fixed slice order,
// computes cos, and reduces relu(cos - posm1) over each row's positive list.
// One atomicAdd per winning block (36 total). Winner resets its counter.
// ---------------------------------------------------------------------------
__global__ void __launch_bounds__(256, 1)
gemm_kernel(const float* __restrict__ embs, float* __restrict__ out) {
    const int tid  = threadIdx.x;
    const int tile = blockIdx.x >> 2;   // 0..35
    const int s    = blockIdx.x & 3;    // k-slice
    int rem = tile, bm = 0;
    while (rem >= NT - bm) { rem -= NT - bm; bm++; }
    const int bn = bm + rem;
    const int k0 = s * KLEN;

    // Staging roles: 128 threads per operand (A: tid<128, B: tid>=128).
    const int tsel = tid >> 7;
    const int tid7 = tid & 127;
    const int kb   = tid7 & 7;          // k-quad (coalesced gmem dim)
    const int rb   = tid7 >> 3;         // row-quad
    const int baserow = (tsel ? bn : bm) * TILE + 4 * rb;
    const float* __restrict__ gsrc = embs + baserow * DDIM + k0 + 4 * kb;

    __shared__ float4 Ash4[32 * 16];    // [k][quad] XOR-swizzled, 8 KB
    __shared__ float4 Bsh4[32 * 16];
    float4* const dst = tsel ? Bsh4 : Ash4;

    const int tx = tid & 15;
    const int ty = tid >> 4;

    float acc[4][4];
#pragma unroll
    for (int i = 0; i < 4; i++)
#pragma unroll
        for (int j = 0; j < 4; j++) acc[i][j] = 0.f;

    for (int kk = 0; kk < KLEN; kk += 32) {
        float4 v0 = *(const float4*)(gsrc + kk);
        float4 v1 = *(const float4*)(gsrc + DDIM + kk);
        float4 v2 = *(const float4*)(gsrc + 2 * DDIM + kk);
        float4 v3 = *(const float4*)(gsrc + 3 * DDIM + kk);
        __syncthreads();                 // previous chunk fully consumed
        const int q = rb ^ kb;           // swizzle: conflict-free stores+reads
        dst[(4 * kb + 0) * 16 + q] = make_float4(v0.x, v1.x, v2.x, v3.x);
        dst[(4 * kb + 1) * 16 + q] = make_float4(v0.y, v1.y, v2.y, v3.y);
        dst[(4 * kb + 2) * 16 + q] = make_float4(v0.z, v1.z, v2.z, v3.z);
        dst[(4 * kb + 3) * 16 + q] = make_float4(v0.w, v1.w, v2.w, v3.w);
        __syncthreads();

#pragma unroll
        for (int k = 0; k < 32; k++) {
            const int sw = (k >> 2) & 7;
            float4 a = Ash4[k * 16 + (ty ^ sw)];
            float4 b = Bsh4[k * 16 + (tx ^ sw)];
            acc[0][0] += a.x * b.x; acc[0][1] += a.x * b.y;
            acc[0][2] += a.x * b.z; acc[0][3] += a.x * b.w;
            acc[1][0] += a.y * b.x; acc[1][1] += a.y * b.y;
            acc[1][2] += a.y * b.z; acc[1][3] += a.y * b.w;
            acc[2][0] += a.z * b.x; acc[2][1] += a.z * b.y;
            acc[2][2] += a.z * b.z; acc[2][3] += a.z * b.w;
            acc[3][0] += a.w * b.x; acc[3][1] += a.w * b.y;
            acc[3][2] += a.w * b.z; acc[3][3] += a.w * b.w;
        }
    }

    float* __restrict__ outp = g_part + s * (NROWS * NROWS);
    const int row0 = bm * TILE + 4 * ty;
    const int col0 = bn * TILE + 4 * tx;
#pragma unroll
    for (int i = 0; i < 4; i++)
        *(float4*)&outp[(row0 + i) * NROWS + col0] =
            make_float4(acc[i][0], acc[i][1], acc[i][2], acc[i][3]);

    // ---- arrival counter: last slice-block of this tile does the reduction
    __threadfence();                     // publish partial stores
    __syncthreads();                     // all threads' fences done
    __shared__ int s_win;
    if (tid == 0) s_win = (atomicAdd(&g_cnt[tile], 1) == KSPLIT - 1);
    __syncthreads();
    if (!s_win) return;
    __threadfence();                     // acquire peers' stores

    // ---- fused triplet reduction over this 64x64 tile
    float4 invR4 = *(const float4*)&g_inv[row0];
    int4   clsR4 = *(const int4*)&g_cls[row0];
    int4   npR4  = *(const int4*)&g_np[row0];
    float4 invC4 = *(const float4*)&g_inv[col0];
    int4   clsC4 = *(const int4*)&g_cls[col0];
    const float invR[4] = {invR4.x, invR4.y, invR4.z, invR4.w};
    const int   clsR[4] = {clsR4.x, clsR4.y, clsR4.z, clsR4.w};
    const int   npR[4]  = {npR4.x,  npR4.y,  npR4.z,  npR4.w};
    const float invC[4] = {invC4.x, invC4.y, invC4.z, invC4.w};
    const int   clsC[4] = {clsC4.x, clsC4.y, clsC4.z, clsC4.w};

    float ssum = 0.f;
#pragma unroll
    for (int i = 0; i < 4; i++) {
        const int R = row0 + i;
        // fixed slice order -> deterministic dot sums
        float4 d0 = *(const float4*)&g_part[0 * (NROWS * NROWS) + R * NROWS + col0];
        float4 d1 = *(const float4*)&g_part[1 * (NROWS * NROWS) + R * NROWS + col0];
        float4 d2 = *(const float4*)&g_part[2 * (NROWS * NROWS) + R * NROWS + col0];
        float4 d3 = *(const float4*)&g_part[3 * (NROWS * NROWS) + R * NROWS + col0];
        float d[4] = {((d0.x + d1.x) + d2.x) + d3.x,
                      ((d0.y + d1.y) + d2.y) + d3.y,
                      ((d0.z + d1.z) + d2.z) + d3.z,
                      ((d0.w + d1.w) + d2.w) + d3.w};
        const float* __restrict__ pm1 = g_posm1[R];
        const int np = npR[i];
#pragma unroll
        for (int j = 0; j < 4; j++) {
            const int C = col0 + j;
            if (C > R && clsC[j] != clsR[i]) {       // valid negative
                float cosv = d[j] * invR[i] * invC[j];
                for (int p = 0; p < np; p++)
                    ssum += fmaxf(cosv - pm1[p], 0.0f);
            }
        }
    }

    // block reduce + one atomic per winning block
    __shared__ float s_red[8];
#pragma unroll
    for (int o = 16; o; o >>= 1) ssum += __shfl_xor_sync(0xffffffffu, ssum, o);
    if ((tid & 31) == 0) s_red[tid >> 5] = ssum;
    __syncthreads();
    if (tid < 8) {
        float v = s_red[tid];
#pragma unroll
        for (int o = 4; o; o >>= 1) v += __shfl_xor_sync(0xffu, v, o);
        if (tid == 0) {
            atomicAdd(out, v);
            g_cnt[tile] = 0;             // reset for next graph replay
        }
    }
}

extern "C" void kernel_launch(void* const* d_in, const int* in_sizes, int n_in,
                              void* d_out, int out_size) {
    const float* embs = (const float*)d_in[0];
    const void*  indices = d_in[1];
    float* out = (float*)d_out;

    prep_kernel<<<64, 256>>>(embs, indices, out);
    gemm_kernel<<<GEMM_GRID, 256>>>(embs, out);
}

// round 10
// speedup vs baseline: 1.0469x; 1.0469x over previous
#include <cuda_runtime.h>

#define NROWS  512
#define DDIM   512
#define TILE   64
#define NT     8            // 512/64 tile-rows
#define NTILES 36           // upper triangle of 8x8
#define KSPLIT 4
#define KLEN   128          // 512/KSPLIT
#define GEMM_GRID (NTILES * KSPLIT)   // 144 blocks ~ one wave
#define POSCAP 32           // max positives per anchor (expected ~4)

// Scratch (allocation-free rule: __device__ globals)
__device__ float g_part[KSPLIT * NROWS * NROWS];  // k-split partial dots
__device__ float g_inv[NROWS];                    // 1/max(norm,eps)
__device__ int   g_cls[NROWS];                    // class ids (normalized int)
__device__ float g_posm1[NROWS][POSCAP];          // cos(pos) - 1  (margin baked)
__device__ int   g_np[NROWS];                     // positives count per anchor
__device__ int   g_cnt[NTILES];                   // tile arrival counters (winners reset)

// ---------------------------------------------------------------------------
// Kernel A: prep. 64 blocks x 256 threads, warp-per-anchor (i = w*64 + bid).
// Per warp: row-i norm, ballot-compact positive j's (same class, j > i),
// compute cos(i,j) directly from embs. Stores posm1 = cos - 1, np, inv.
// Block 0: publish g_cls, zero out. Probe is per-block (self-contained).
// ---------------------------------------------------------------------------
__global__ void prep_kernel(const float* __restrict__ embs,
                            const void* __restrict__ idxraw,
                            float* __restrict__ out) {
    const int tid  = threadIdx.x;
    const int w    = tid >> 5;
    const int lane = tid & 31;

    __shared__ int s_cls[NROWS];
    __shared__ int fl;
    __shared__ int s_pj[8][POSCAP];

    // Dtype probe: odd int32 positions within the first 2048 bytes.
    // int64 layout -> all zero high words; int32 -> real class ids.
    if (tid == 0) fl = 0;
    __syncthreads();
    if (((const int*)idxraw)[2 * tid + 1] != 0) atomicOr(&fl, 1);
    __syncthreads();
    const int is32 = fl;
    const int* __restrict__ i32p = (const int*)idxraw;
    const long long* __restrict__ i64p = (const long long*)idxraw;

#pragma unroll
    for (int e = 0; e < 2; e++) {
        int r = tid + e * 256;
        s_cls[r] = is32 ? i32p[r] : (int)i64p[r];
    }
    __syncthreads();
    if (blockIdx.x == 0) {
        if (tid == 0) *out = 0.0f;
#pragma unroll
        for (int e = 0; e < 2; e++) { int r = tid + e * 256; g_cls[r] = s_cls[r]; }
    }

    const int i = w * 64 + blockIdx.x;     // anchor
    const float* __restrict__ rowp = embs + i * DDIM + lane * 4;
    float4 av[4];
#pragma unroll
    for (int q = 0; q < 4; q++) av[q] = *(const float4*)(rowp + q * 128);

    float dii = 0.f;
#pragma unroll
    for (int q = 0; q < 4; q++)
        dii += av[q].x * av[q].x + av[q].y * av[q].y +
               av[q].z * av[q].z + av[q].w * av[q].w;
#pragma unroll
    for (int o = 16; o; o >>= 1) dii += __shfl_xor_sync(0xffffffffu, dii, o);
    const float invi = 1.0f / fmaxf(sqrtf(dii), 1e-8f);
    if (lane == 0) g_inv[i] = invi;

    // Ballot-compact positive indices (uniform 16 iterations, no divergence).
    const int ci = s_cls[i];
    int np = 0;
#pragma unroll
    for (int slot = 0; slot < 16; slot++) {
        int j = i + 1 + lane + slot * 32;
        bool match = (j < NROWS) && (s_cls[j] == ci);
        unsigned m = __ballot_sync(0xffffffffu, match);
        if (match) {
            int off = np + __popc(m & ((1u << lane) - 1u));
            if (off < POSCAP) s_pj[w][off] = j;
        }
        np += __popc(m);
    }
    if (np > POSCAP) np = POSCAP;
    __syncwarp();
    if (lane == 0) g_np[i] = np;

    // Positive cos values: full warp per positive (dot(i,j) and dot(j,j)).
    for (int p = 0; p < np; p++) {
        int j = s_pj[w][p];
        const float* __restrict__ rj = embs + j * DDIM + lane * 4;
        float dij = 0.f, djj = 0.f;
#pragma unroll
        for (int q = 0; q < 4; q++) {
            float4 b = *(const float4*)(rj + q * 128);
            dij += av[q].x * b.x + av[q].y * b.y + av[q].z * b.z + av[q].w * b.w;
            djj += b.x * b.x + b.y * b.y + b.z * b.z + b.w * b.w;
        }
#pragma unroll
        for (int o = 16; o; o >>= 1) {
            dij += __shfl_xor_sync(0xffffffffu, dij, o);
            djj += __shfl_xor_sync(0xffffffffu, djj, o);
        }
        if (lane == 0) {
            float invj = 1.0f / fmaxf(sqrtf(djj), 1e-8f);
            g_posm1[i][p] = dij * invi * invj - 1.0f;   // margin baked in
        }
    }
}

// ---------------------------------------------------------------------------
// Kernel B: GEMM + fused triplet reduction. 144 blocks x 256 threads.
// Mainloop identical to R8/R9. Winner (last slice arriver per tile) stages
// posm1/inv/cls/np into SHARED (reusing the dead GEMM staging buffers), then
// runs the triplet reduction entirely from registers + broadcast LDS.
// One atomicAdd per winning block (36 total). Winner resets its counter.
// ---------------------------------------------------------------------------
__global__ void __launch_bounds__(256, 1)
gemm_kernel(const float* __restrict__ embs, float* __restrict__ out) {
    const int tid  = threadIdx.x;
    const int tile = blockIdx.x >> 2;   // 0..35
    const int s    = blockIdx.x & 3;    // k-slice
    int rem = tile, bm = 0;
    while (rem >= NT - bm) { rem -= NT - bm; bm++; }
    const int bn = bm + rem;
    const int k0 = s * KLEN;

    // Staging roles: 128 threads per operand (A: tid<128, B: tid>=128).
    const int tsel = tid >> 7;
    const int tid7 = tid & 127;
    const int kb   = tid7 & 7;          // k-quad (coalesced gmem dim)
    const int rb   = tid7 >> 3;         // row-quad
    const int baserow = (tsel ? bn : bm) * TILE + 4 * rb;
    const float* __restrict__ gsrc = embs + baserow * DDIM + k0 + 4 * kb;

    __shared__ float4 Ash4[32 * 16];    // [k][quad] XOR-swizzled, 8 KB
    __shared__ float4 Bsh4[32 * 16];    // 8 KB
    float4* const dst = tsel ? Bsh4 : Ash4;

    const int tx = tid & 15;
    const int ty = tid >> 4;

    float acc[4][4];
#pragma unroll
    for (int i = 0; i < 4; i++)
#pragma unroll
        for (int j = 0; j < 4; j++) acc[i][j] = 0.f;

    for (int kk = 0; kk < KLEN; kk += 32) {
        float4 v0 = *(const float4*)(gsrc + kk);
        float4 v1 = *(const float4*)(gsrc + DDIM + kk);
        float4 v2 = *(const float4*)(gsrc + 2 * DDIM + kk);
        float4 v3 = *(const float4*)(gsrc + 3 * DDIM + kk);
        __syncthreads();                 // previous chunk fully consumed
        const int q = rb ^ kb;           // swizzle: conflict-free stores+reads
        dst[(4 * kb + 0) * 16 + q] = make_float4(v0.x, v1.x, v2.x, v3.x);
        dst[(4 * kb + 1) * 16 + q] = make_float4(v0.y, v1.y, v2.y, v3.y);
        dst[(4 * kb + 2) * 16 + q] = make_float4(v0.z, v1.z, v2.z, v3.z);
        dst[(4 * kb + 3) * 16 + q] = make_float4(v0.w, v1.w, v2.w, v3.w);
        __syncthreads();

#pragma unroll
        for (int k = 0; k < 32; k++) {
            const int sw = (k >> 2) & 7;
            float4 a = Ash4[k * 16 + (ty ^ sw)];
            float4 b = Bsh4[k * 16 + (tx ^ sw)];
            acc[0][0] += a.x * b.x; acc[0][1] += a.x * b.y;
            acc[0][2] += a.x * b.z; acc[0][3] += a.x * b.w;
            acc[1][0] += a.y * b.x; acc[1][1] += a.y * b.y;
            acc[1][2] += a.y * b.z; acc[1][3] += a.y * b.w;
            acc[2][0] += a.z * b.x; acc[2][1] += a.z * b.y;
            acc[2][2] += a.z * b.z; acc[2][3] += a.z * b.w;
            acc[3][0] += a.w * b.x; acc[3][1] += a.w * b.y;
            acc[3][2] += a.w * b.z; acc[3][3] += a.w * b.w;
        }
    }

    float* __restrict__ outp = g_part + s * (NROWS * NROWS);
    const int row0 = bm * TILE + 4 * ty;
    const int col0 = bn * TILE + 4 * tx;
#pragma unroll
    for (int i = 0; i < 4; i++)
        *(float4*)&outp[(row0 + i) * NROWS + col0] =
            make_float4(acc[i][0], acc[i][1], acc[i][2], acc[i][3]);

    // ---- arrival counter: last slice-block of this tile does the reduction
    __threadfence();                     // publish partial stores
    __syncthreads();                     // all threads' fences done
    __shared__ int s_win;
    if (tid == 0) s_win = (atomicAdd(&g_cnt[tile], 1) == KSPLIT - 1);
    __syncthreads();
    if (!s_win) return;
    __threadfence();                     // acquire peers' stores

    // ---- stage per-tile metadata into shared (reuse dead GEMM buffers) ----
    // Ash4 region (8 KB): posm1 for the tile's 64 rows  [64][POSCAP]
    // Bsh4 region: invR[64] invC[64] (float), clsR[64] clsC[64] npv[64] (int)
    float* const pm1s  = (float*)Ash4;
    float* const invRs = (float*)Bsh4;
    float* const invCs = invRs + 64;
    int*   const clsRs = (int*)(invCs + 64);
    int*   const clsCs = clsRs + 64;
    int*   const npvs  = clsCs + 64;

    const int rbase = bm * TILE;
    const int cbase = bn * TILE;
    {
        const float4* __restrict__ src = (const float4*)&g_posm1[rbase][0];
        float4* const dst4 = (float4*)pm1s;
#pragma unroll
        for (int e = 0; e < 2; e++)                 // 512 float4 = 64*POSCAP floats
            dst4[tid + e * 256] = src[tid + e * 256];
        if (tid < 64) {
            invRs[tid] = g_inv[rbase + tid];
            invCs[tid] = g_inv[cbase + tid];
            clsRs[tid] = g_cls[rbase + tid];
            clsCs[tid] = g_cls[cbase + tid];
            npvs[tid]  = g_np[rbase + tid];
        }
    }
    __syncthreads();

    // ---- fused triplet reduction over this 64x64 tile (shared/regs only) --
    float ssum = 0.f;
#pragma unroll
    for (int i = 0; i < 4; i++) {
        const int rloc = 4 * ty + i;
        const int R = rbase + rloc;
        // fixed slice order -> deterministic dot sums
        float4 d0 = *(const float4*)&g_part[0 * (NROWS * NROWS) + R * NROWS + col0];
        float4 d1 = *(const float4*)&g_part[1 * (NROWS * NROWS) + R * NROWS + col0];
        float4 d2 = *(const float4*)&g_part[2 * (NROWS * NROWS) + R * NROWS + col0];
        float4 d3 = *(const float4*)&g_part[3 * (NROWS * NROWS) + R * NROWS + col0];
        float d[4] = {((d0.x + d1.x) + d2.x) + d3.x,
                      ((d0.y + d1.y) + d2.y) + d3.y,
                      ((d0.z + d1.z) + d2.z) + d3.z,
                      ((d0.w + d1.w) + d2.w) + d3.w};
        const int   np = npvs[rloc];
        const int   cR = clsRs[rloc];
        const float iR = invRs[rloc];
        const float* __restrict__ prow = pm1s + rloc * POSCAP;
#pragma unroll
        for (int j = 0; j < 4; j++) {
            const int cloc = 4 * tx + j;
            if (cbase + cloc > R && clsCs[cloc] != cR) {   // valid negative
                float cosv = d[j] * iR * invCs[cloc];
                for (int p = 0; p < np; p++)               // broadcast LDS, pipelined
                    ssum += fmaxf(cosv - prow[p], 0.0f);
            }
        }
    }

    // block reduce + one atomic per winning block
    __shared__ float s_red[8];
#pragma unroll
    for (int o = 16; o; o >>= 1) ssum += __shfl_xor_sync(0xffffffffu, ssum, o);
    if ((tid & 31) == 0) s_red[tid >> 5] = ssum;
    __syncthreads();
    if (tid < 8) {
        float v = s_red[tid];
#pragma unroll
        for (int o = 4; o; o >>= 1) v += __shfl_xor_sync(0xffu, v, o);
        if (tid == 0) {
            atomicAdd(out, v);
            g_cnt[tile] = 0;             // reset for next graph replay
        }
    }
}

extern "C" void kernel_launch(void* const* d_in, const int* in_sizes, int n_in,
                              void* d_out, int out_size) {
    const float* embs = (const float*)d_in[0];
    const void*  indices = d_in[1];
    float* out = (float*)d_out;

    prep_kernel<<<64, 256>>>(embs, indices, out);
    gemm_kernel<<<GEMM_GRID, 256>>>(embs, out);
}

// round 13
// speedup vs baseline: 1.6000x; 1.5283x over previous
#include <cuda_runtime.h>

#define NROWS  512
#define DDIM   512
#define TILE   64
#define NT     8            // 512/64 tile-rows
#define NTILES 36           // upper triangle of 8x8
#define KSPLIT 4
#define KLEN   128          // 512/KSPLIT
#define GEMM_GRID (NTILES * KSPLIT)   // 144 blocks ~ one wave

// Scratch (allocation-free rule: __device__ globals)
__device__ float g_part[KSPLIT * NROWS * NROWS];  // k-split partial dots
__device__ float g_diag[KSPLIT][NROWS];           // k-split partial diagonal
__device__ int   g_idx32;                         // 1 if indices are int32

// ---------------------------------------------------------------------------
// Kernel 1: dot GEMM. 144 blocks x 256 threads. (Unchanged from R8 best.)
// 64x64 upper-triangle tiles (36) x 4-way k-split. 4x4 register micro-tile:
// per k, 2x LDS.128 + 16 FFMA (2 B/FMA) -> FFMA-bound. XOR-swizzled staging.
// Block 0 zeroes the output scalar and probes the indices dtype.
// ---------------------------------------------------------------------------
__global__ void __launch_bounds__(256, 1)
gemm_kernel(const float* __restrict__ embs,
            const int* __restrict__ idx32view,
            float* __restrict__ out) {
    const int tid = threadIdx.x;

    if (blockIdx.x == 0) {
        // Dtype probe: odd int32 positions within the first 2048 bytes.
        // int64 layout -> all zero high words; int32 -> real class ids.
        __shared__ int fl;
        if (tid == 0) { fl = 0; *out = 0.0f; }
        __syncthreads();
        if (idx32view[2 * tid + 1] != 0) atomicOr(&fl, 1);
        __syncthreads();
        if (tid == 0) g_idx32 = fl;
    }

    const int tile = blockIdx.x >> 2;   // 0..35
    const int s    = blockIdx.x & 3;    // k-slice
    int rem = tile, bm = 0;
    while (rem >= NT - bm) { rem -= NT - bm; bm++; }
    const int bn = bm + rem;
    const int k0 = s * KLEN;

    // Staging roles: 128 threads per operand (A: tid<128, B: tid>=128).
    const int tsel = tid >> 7;
    const int tid7 = tid & 127;
    const int kb   = tid7 & 7;          // k-quad (coalesced gmem dim)
    const int rb   = tid7 >> 3;         // row-quad
    const int baserow = (tsel ? bn : bm) * TILE + 4 * rb;
    const float* __restrict__ gsrc = embs + baserow * DDIM + k0 + 4 * kb;

    __shared__ float4 Ash4[32 * 16];    // [k][quad] XOR-swizzled, 8 KB
    __shared__ float4 Bsh4[32 * 16];
    float4* const dst = tsel ? Bsh4 : Ash4;

    const int tx = tid & 15;
    const int ty = tid >> 4;

    float acc[4][4];
#pragma unroll
    for (int i = 0; i < 4; i++)
#pragma unroll
        for (int j = 0; j < 4; j++) acc[i][j] = 0.f;

    for (int kk = 0; kk < KLEN; kk += 32) {
        float4 v0 = *(const float4*)(gsrc + kk);
        float4 v1 = *(const float4*)(gsrc + DDIM + kk);
        float4 v2 = *(const float4*)(gsrc + 2 * DDIM + kk);
        float4 v3 = *(const float4*)(gsrc + 3 * DDIM + kk);
        __syncthreads();                 // previous chunk fully consumed
        const int q = rb ^ kb;           // swizzle: conflict-free stores+reads
        dst[(4 * kb + 0) * 16 + q] = make_float4(v0.x, v1.x, v2.x, v3.x);
        dst[(4 * kb + 1) * 16 + q] = make_float4(v0.y, v1.y, v2.y, v3.y);
        dst[(4 * kb + 2) * 16 + q] = make_float4(v0.z, v1.z, v2.z, v3.z);
        dst[(4 * kb + 3) * 16 + q] = make_float4(v0.w, v1.w, v2.w, v3.w);
        __syncthreads();

#pragma unroll
        for (int k = 0; k < 32; k++) {
            const int sw = (k >> 2) & 7;
            float4 a = Ash4[k * 16 + (ty ^ sw)];
            float4 b = Bsh4[k * 16 + (tx ^ sw)];
            acc[0][0] += a.x * b.x; acc[0][1] += a.x * b.y;
            acc[0][2] += a.x * b.z; acc[0][3] += a.x * b.w;
            acc[1][0] += a.y * b.x; acc[1][1] += a.y * b.y;
            acc[1][2] += a.y * b.z; acc[1][3] += a.y * b.w;
            acc[2][0] += a.z * b.x; acc[2][1] += a.z * b.y;
            acc[2][2] += a.z * b.z; acc[2][3] += a.z * b.w;
            acc[3][0] += a.w * b.x; acc[3][1] += a.w * b.y;
            acc[3][2] += a.w * b.z; acc[3][3] += a.w * b.w;
        }
    }

    float* __restrict__ outp = g_part + s * (NROWS * NROWS);
    const int row0 = bm * TILE + 4 * ty;
    const int col0 = bn * TILE + 4 * tx;
#pragma unroll
    for (int i = 0; i < 4; i++)
        *(float4*)&outp[(row0 + i) * NROWS + col0] =
            make_float4(acc[i][0], acc[i][1], acc[i][2], acc[i][3]);

    if (bm == bn && tx == ty) {
#pragma unroll
        for (int d = 0; d < 4; d++) g_diag[s][row0 + d] = acc[d][d];
    }
}

// ---------------------------------------------------------------------------
// Kernel 2: triplet sum, warp-per-anchor. 128 blocks x 128 threads
// (was 64x256 in R8): same per-warp code path, 2x the SM coverage for this
// latency-bound kernel. Balanced mapping: anchor = w*128 + blockIdx.x.
// Phase A: batched LDGs sum the 4 k-split partials per slot (deep MLP).
// Phase B: uniform ballot compaction of positives. Hot loop: np x 16
// unrolled register fmax. One atomicAdd per block (128 total).
// ---------------------------------------------------------------------------
__global__ void triplet_kernel(const void* __restrict__ idxraw,
                               float* __restrict__ out) {
    const int tid  = threadIdx.x;       // 0..127
    const int w    = tid >> 5;          // warp 0..3
    const int lane = tid & 31;

    __shared__ float s_inv[NROWS];
    __shared__ int   s_cls[NROWS];
    __shared__ float s_pos[4][32];
    __shared__ float s_wsum[4];

    const int is32 = g_idx32;
    const int* __restrict__ i32 = (const int*)idxraw;
    const long long* __restrict__ i64 = (const long long*)idxraw;

#pragma unroll
    for (int e = 0; e < 4; e++) {
        int r = tid + e * 128;
        float d = 0.f;
#pragma unroll
        for (int p = 0; p < KSPLIT; p++) d += g_diag[p][r];   // coalesced
        s_inv[r] = 1.0f / fmaxf(sqrtf(d), 1e-8f);
        s_cls[r] = is32 ? i32[r] : (int)i64[r];
    }
    __syncthreads();

    const int i = w * 128 + blockIdx.x;       // balanced anchor mapping
    const int   ci   = s_cls[i];
    const float invi = s_inv[i];
    const int   rowbase = i * NROWS;

    // Phase A: batched partial-sum loads; no warp collectives here.
    float c[16];
#pragma unroll
    for (int slot = 0; slot < 16; slot++) {
        int j = i + 1 + lane + slot * 32;
        float sum = 0.f;
        if (j < NROWS) {
#pragma unroll
            for (int p = 0; p < KSPLIT; p++)
                sum += g_part[p * (NROWS * NROWS) + rowbase + j];
            sum *= invi * s_inv[j];
        }
        c[slot] = sum;
    }

    // Phase B: uniform ballot compaction (all lanes hit every ballot).
    int np = 0;
#pragma unroll
    for (int slot = 0; slot < 16; slot++) {
        int j = i + 1 + lane + slot * 32;
        bool valid = (j < NROWS);
        bool match = valid && (s_cls[j] == ci);
        unsigned mask = __ballot_sync(0xffffffffu, match);
        if (match) {
            int off = np + __popc(mask & ((1u << lane) - 1u));
            if (off < 32) s_pos[w][off] = c[slot];
        }
        np += __popc(mask);
        c[slot] = (valid && !match) ? (c[slot] + 1.0f) : -1e30f;  // sentinel
    }
    if (np > 32) np = 32;   // capacity guard (expected np ~ 4)
    __syncwarp();

    // Hot loop: np broadcast-LDS reads, 16 unrolled register fmax each.
    float s0 = 0.f, s1 = 0.f;
    for (int p = 0; p < np; p++) {
        float bp = s_pos[w][p];
#pragma unroll
        for (int slot = 0; slot < 16; slot += 2) {
            s0 += fmaxf(c[slot]     - bp, 0.0f);
            s1 += fmaxf(c[slot + 1] - bp, 0.0f);
        }
    }
    float s = s0 + s1;

#pragma unroll
    for (int o = 16; o; o >>= 1) s += __shfl_xor_sync(0xffffffffu, s, o);
    if (lane == 0) s_wsum[w] = s;
    __syncthreads();

    if (tid < 4) {
        float v = s_wsum[tid];
#pragma unroll
        for (int o = 2; o; o >>= 1) v += __shfl_xor_sync(0xfu, v, o);
        if (tid == 0) atomicAdd(out, v);   // one atomic per block (128 total)
    }
}

extern "C" void kernel_launch(void* const* d_in, const int* in_sizes, int n_in,
                              void* d_out, int out_size) {
    const float* embs = (const float*)d_in[0];
    const void*  indices = d_in[1];
    float* out = (float*)d_out;

    gemm_kernel<<<GEMM_GRID, 256>>>(embs, (const int*)indices, out);
    triplet_kernel<<<128, 128>>>(indices, out);
}

// round 14
// speedup vs baseline: 1.8713x; 1.1696x over previous
#include <cuda_runtime.h>

#define NROWS  512
#define DDIM   512
#define TILE   64
#define NT     8            // 512/64 tile-rows
#define NTILES 36           // upper triangle of 8x8
#define KSPLIT 4
#define KLEN   128          // 512/KSPLIT
#define GRID   (NTILES * KSPLIT)   // 144 blocks < 148 SMs -> co-resident, spin-safe

// Scratch (allocation-free rule: __device__ globals)
__device__ float g_part[KSPLIT * NROWS * NROWS];  // k-split partial dots
__device__ float g_diag[KSPLIT][NROWS];           // k-split partial diagonal
__device__ int   g_bar  = 0;                      // phase barrier (reset each call)
__device__ int   g_done = 0;                      // completion counter (reset each call)

// ---------------------------------------------------------------------------
// Fused kernel: R8 GEMM (phase 1) + device-wide spin barrier + triplet
// reduction spread over ALL 144 blocks (phase 2). 144 blocks x 256 threads.
//
// Phase 1: 64x64 upper-triangle tiles (36) x 4-way k-split, 4x4 register
// micro-tile, XOR-swizzled staging (2 B/FMA -> FFMA-bound). Diagonal tiles
// emit k-split diag partials. Block 0 zeroes the output scalar.
//
// Barrier: one-arrival-per-block atomic + spin (all 144 blocks co-resident).
//
// Phase 2: 512 anchor-slots over 144 blocks (slot = bid + 144*w, w<4;
// anchor = slot*293 & 511 balances heavy/light rows). Per warp: batched
// partial-sum loads, uniform ballot compaction of positives, np x 16
// register fmax hot loop. One atomicAdd per block. Phase-2 tables overlay
// the dead GEMM staging smem. Last g_done arriver resets counters (replay).
// ---------------------------------------------------------------------------
__global__ void __launch_bounds__(256, 1)
fused_kernel(const float* __restrict__ embs,
             const void* __restrict__ idxraw,
             float* __restrict__ out) {
    const int tid = threadIdx.x;          // 0..255
    const int bid = blockIdx.x;

    __shared__ float4 Ash4[32 * 16];      // 8 KB (phase 1: A stage; phase 2: tables)
    __shared__ float4 Bsh4[32 * 16];      // 8 KB

    // ======================= Phase 1: GEMM =======================
    {
        if (bid == 0 && tid == 0) *out = 0.0f;   // published by the barrier fence

        const int tile = bid >> 2;        // 0..35
        const int s    = bid & 3;         // k-slice
        int rem = tile, bm = 0;
        while (rem >= NT - bm) { rem -= NT - bm; bm++; }
        const int bn = bm + rem;
        const int k0 = s * KLEN;

        // Staging roles: 128 threads per operand (A: tid<128, B: tid>=128).
        const int tsel = tid >> 7;
        const int tid7 = tid & 127;
        const int kb   = tid7 & 7;        // k-quad (coalesced gmem dim)
        const int rb   = tid7 >> 3;       // row-quad
        const int baserow = (tsel ? bn : bm) * TILE + 4 * rb;
        const float* __restrict__ gsrc = embs + baserow * DDIM + k0 + 4 * kb;
        float4* const dst = tsel ? Bsh4 : Ash4;

        const int tx = tid & 15;
        const int ty = tid >> 4;

        float acc[4][4];
#pragma unroll
        for (int i = 0; i < 4; i++)
#pragma unroll
            for (int j = 0; j < 4; j++) acc[i][j] = 0.f;

        for (int kk = 0; kk < KLEN; kk += 32) {
            float4 v0 = *(const float4*)(gsrc + kk);
            float4 v1 = *(const float4*)(gsrc + DDIM + kk);
            float4 v2 = *(const float4*)(gsrc + 2 * DDIM + kk);
            float4 v3 = *(const float4*)(gsrc + 3 * DDIM + kk);
            __syncthreads();              // previous chunk fully consumed
            const int q = rb ^ kb;        // swizzle: conflict-free stores+reads
            dst[(4 * kb + 0) * 16 + q] = make_float4(v0.x, v1.x, v2.x, v3.x);
            dst[(4 * kb + 1) * 16 + q] = make_float4(v0.y, v1.y, v2.y, v3.y);
            dst[(4 * kb + 2) * 16 + q] = make_float4(v0.z, v1.z, v2.z, v3.z);
            dst[(4 * kb + 3) * 16 + q] = make_float4(v0.w, v1.w, v2.w, v3.w);
            __syncthreads();

#pragma unroll
            for (int k = 0; k < 32; k++) {
                const int sw = (k >> 2) & 7;
                float4 a = Ash4[k * 16 + (ty ^ sw)];
                float4 b = Bsh4[k * 16 + (tx ^ sw)];
                acc[0][0] += a.x * b.x; acc[0][1] += a.x * b.y;
                acc[0][2] += a.x * b.z; acc[0][3] += a.x * b.w;
                acc[1][0] += a.y * b.x; acc[1][1] += a.y * b.y;
                acc[1][2] += a.y * b.z; acc[1][3] += a.y * b.w;
                acc[2][0] += a.z * b.x; acc[2][1] += a.z * b.y;
                acc[2][2] += a.z * b.z; acc[2][3] += a.z * b.w;
                acc[3][0] += a.w * b.x; acc[3][1] += a.w * b.y;
                acc[3][2] += a.w * b.z; acc[3][3] += a.w * b.w;
            }
        }

        float* __restrict__ outp = g_part + s * (NROWS * NROWS);
        const int row0 = bm * TILE + 4 * ty;
        const int col0 = bn * TILE + 4 * tx;
#pragma unroll
        for (int i = 0; i < 4; i++)
            *(float4*)&outp[(row0 + i) * NROWS + col0] =
                make_float4(acc[i][0], acc[i][1], acc[i][2], acc[i][3]);

        if (bm == bn && tx == ty) {
#pragma unroll
            for (int d = 0; d < 4; d++) g_diag[s][row0 + d] = acc[d][d];
        }
    }

    // =================== Device-wide barrier ===================
    __syncthreads();
    __threadfence();                      // publish g_part / g_diag / *out
    if (tid == 0) {
        atomicAdd(&g_bar, 1);
        while (*(volatile int*)&g_bar < GRID) { }
    }
    __syncthreads();
    __threadfence();                      // acquire other blocks' writes

    // ======================= Phase 2: triplet =======================
    {
        const int w    = tid >> 5;        // warp 0..7
        const int lane = tid & 31;

        // Overlay tables onto the dead GEMM staging smem (Ash4 = 8 KB).
        float* const s_inv = (float*)Ash4;            // 512 floats (2 KB)
        int*   const s_cls = (int*)(s_inv + NROWS);   // 512 ints   (2 KB)
        float* const s_pos = (float*)(s_cls + NROWS); // 8 warps x 32 (1 KB)
        __shared__ float s_wsum[8];
        __shared__ int   fl;

        // Dtype probe (per-block): odd int32 positions within the first
        // 2048 bytes. int64 layout -> all zero high words; int32 -> ids.
        if (tid == 0) fl = 0;
        __syncthreads();
        if (((const int*)idxraw)[2 * tid + 1] != 0) atomicOr(&fl, 1);
        __syncthreads();
        const int is32 = fl;
        const int* __restrict__ i32 = (const int*)idxraw;
        const long long* __restrict__ i64 = (const long long*)idxraw;

#pragma unroll
        for (int e = 0; e < 2; e++) {
            int r = tid + e * 256;
            float d = 0.f;
#pragma unroll
            for (int p = 0; p < KSPLIT; p++) d += g_diag[p][r];   // coalesced
            s_inv[r] = 1.0f / fmaxf(sqrtf(d), 1e-8f);
            s_cls[r] = is32 ? i32[r] : (int)i64[r];
        }
        __syncthreads();

        float wsum = 0.f;
        const int slot = bid + 144 * w;   // warps 0..3 carry slots; 80*4+64*3=512
        if (w < 4 && slot < 512) {
            const int i = (slot * 293) & 511;   // odd multiplier: bijection, balances load
            const int   ci   = s_cls[i];
            const float invi = s_inv[i];
            const int   rowbase = i * NROWS;

            // Phase A: batched partial-sum loads; no warp collectives here.
            float c[16];
#pragma unroll
            for (int sl = 0; sl < 16; sl++) {
                int j = i + 1 + lane + sl * 32;
                float sum = 0.f;
                if (j < NROWS) {
#pragma unroll
                    for (int p = 0; p < KSPLIT; p++)
                        sum += g_part[p * (NROWS * NROWS) + rowbase + j];
                    sum *= invi * s_inv[j];
                }
                c[sl] = sum;
            }

            // Phase B: uniform ballot compaction (all lanes hit every ballot).
            int np = 0;
#pragma unroll
            for (int sl = 0; sl < 16; sl++) {
                int j = i + 1 + lane + sl * 32;
                bool valid = (j < NROWS);
                bool match = valid && (s_cls[j] == ci);
                unsigned mask = __ballot_sync(0xffffffffu, match);
                if (match) {
                    int off = np + __popc(mask & ((1u << lane) - 1u));
                    if (off < 32) s_pos[w * 32 + off] = c[sl];
                }
                np += __popc(mask);
                c[sl] = (valid && !match) ? (c[sl] + 1.0f) : -1e30f;  // sentinel
            }
            if (np > 32) np = 32;         // capacity guard (expected np ~ 4)
            __syncwarp();

            // Hot loop: np broadcast-LDS reads, 16 unrolled register fmax each.
            float s0 = 0.f, s1 = 0.f;
            for (int p = 0; p < np; p++) {
                float bp = s_pos[w * 32 + p];
#pragma unroll
                for (int sl = 0; sl < 16; sl += 2) {
                    s0 += fmaxf(c[sl]     - bp, 0.0f);
                    s1 += fmaxf(c[sl + 1] - bp, 0.0f);
                }
            }
            wsum = s0 + s1;
        }

#pragma unroll
        for (int o = 16; o; o >>= 1) wsum += __shfl_xor_sync(0xffffffffu, wsum, o);
        if (lane == 0) s_wsum[w] = wsum;
        __syncthreads();
        if (tid < 8) {
            float v = s_wsum[tid];
#pragma unroll
            for (int o = 4; o; o >>= 1) v += __shfl_xor_sync(0xffu, v, o);
            if (tid == 0) atomicAdd(out, v);   // one atomic per block (144 total)
        }
    }

    // ============ Reset counters for next graph replay ============
    // Every block increments g_done only after exiting the spin, so the
    // 144th finisher can safely zero both counters.
    __syncthreads();
    if (tid == 0) {
        int d = atomicAdd(&g_done, 1);
        if (d == GRID - 1) {
            g_bar  = 0;
            g_done = 0;
            __threadfence();
        }
    }
}

extern "C" void kernel_launch(void* const* d_in, const int* in_sizes, int n_in,
                              void* d_out, int out_size) {
    const float* embs = (const float*)d_in[0];
    const void*  indices = d_in[1];
    float* out = (float*)d_out;

    fused_kernel<<<GRID, 256>>>(embs, indices, out);
}